// round 6
// baseline (speedup 1.0000x reference)
#include <cuda_runtime.h>
#include <cstdint>

// FactorizedSpectralConv on GB300 — f32x2-packed radix-2 folded DFTs.
// B=16, C=64, H=W=128, M0=M1=16.

typedef unsigned long long ull;
#define PI2_OVER_128 0.04908738521234051935f  // 2*pi/128
#define SGN2 0x8000000080000000ULL

// Scratch (device globals; allocation-free rule)
__device__ float2 g_Xf[512 * 1024];   // [m][t*16+b], 4 MB
__device__ float2 g_Y [512 * 1024];   // [m][b*64+c], 4 MB
__device__ float2 g_W [512 * 4096];   // [m][c*64+t], 16 MB (transposed weights)

__device__ __forceinline__ ull pk2(float x, float y) {
    ull r; asm("mov.b64 %0,{%1,%2};" : "=l"(r) : "f"(x), "f"(y)); return r;
}
__device__ __forceinline__ void upk2(ull v, float& x, float& y) {
    asm("mov.b64 {%0,%1},%2;" : "=f"(x), "=f"(y) : "l"(v));
}
__device__ __forceinline__ void fma2(ull& d, ull a, ull b) {
    asm("fma.rn.f32x2 %0,%1,%2,%0;" : "+l"(d) : "l"(a), "l"(b));
}
__device__ __forceinline__ ull add2(ull a, ull b) {
    ull d; asm("add.rn.f32x2 %0,%1,%2;" : "=l"(d) : "l"(a), "l"(b)); return d;
}
__device__ __forceinline__ ull sub2(ull a, ull b) {   // a - b via sign-flip + add
    return add2(a, b ^ SGN2);
}

// ---------------------------------------------------------------------------
// K1: forward (blocks 0..1023) + weight transpose (blocks 1024..3071).
// 128 threads. Independent work fused into one launch for overlap.
// ---------------------------------------------------------------------------
__global__ void __launch_bounds__(128) k_fwd_tr(
    const float* __restrict__ X,
    const float* __restrict__ w0r, const float* __restrict__ w0i,
    const float* __restrict__ w1r, const float* __restrict__ w1i) {
    __shared__ __align__(16) ull TWA[64][16];   // (c,-s)/16384, w<64 — 8KB
    __shared__ __align__(16) ull TWB[128][2];   // (c,-s),(s,c) — 2KB
    __shared__ float Xs[128][33];               // lo 0..15, hi 16..31 — 16.9KB
    __shared__ ull   Fw[16][129];               // packed F[ky][h] — 16.5KB

    int tid = threadIdx.x;

    if (blockIdx.x >= 1024) {
        // ---- transpose part: w[c][t][kx0][ky] -> g_W[m][c*64+t] ----
        float (*Tr)[33] = (float(*)[33])&TWA[0][0];   // reuse smem (32x33 floats)
        float (*Ti)[33] = (float(*)[33])&Xs[0][0];
        int bid = blockIdx.x - 1024;
        int arr = bid >> 10;
        int tix = bid & 1023;
        int ctTile = tix >> 3, mTile = tix & 7;
        const float* Sr = arr ? w1r : w0r;
        const float* Si = arr ? w1i : w0i;
        int tx = tid & 31, ty = tid >> 5;       // ty in 0..3
        #pragma unroll
        for (int yy = 0; yy < 8; yy++) {
            int r = ty + yy * 4;
            int row = ctTile * 32 + r, col = mTile * 32 + tx;
            Tr[r][tx] = Sr[row * 256 + col];
            Ti[r][tx] = Si[row * 256 + col];
        }
        __syncthreads();
        #pragma unroll
        for (int yy = 0; yy < 8; yy++) {
            int r = ty + yy * 4;
            int m = arr * 256 + mTile * 32 + r;
            int ct = ctTile * 32 + tx;
            g_W[(size_t)m * 4096 + ct] = make_float2(Tr[tx][r], Ti[tx][r]);
        }
        return;
    }

    // ---- forward part ----
    #pragma unroll
    for (int e = tid; e < 1024; e += 128) {
        int w = e >> 4, k = e & 15;
        float s, c; sincosf(PI2_OVER_128 * (float)((w * k) & 127), &s, &c);
        TWA[w][k] = pk2(c * (1.f / 16384.f), -s * (1.f / 16384.f));
    }
    {
        float s, c; sincosf(PI2_OVER_128 * (float)tid, &s, &c);
        TWB[tid][0] = pk2(c, -s);
        TWB[tid][1] = pk2(s, c);
    }

    const float* Xp = X + (size_t)blockIdx.x * 16384;

    // Phase A: F[h,ky] = sum_{w<64} (X[w] +/- X[w+64]) e^{-2pi i ky w/128}
    ull acc[16];
    #pragma unroll
    for (int k = 0; k < 16; k++) acc[k] = 0;

    for (int c0 = 0; c0 < 64; c0 += 16) {
        __syncthreads();
        #pragma unroll
        for (int p = 0; p < 8; p++) {
            int i = p * 128 + tid;
            int r = i >> 3, q = i & 7;
            const float* src = (q < 4) ? (Xp + r * 128 + c0 + q * 4)
                                       : (Xp + r * 128 + c0 + 64 + (q - 4) * 4);
            float4 v = *(const float4*)src;
            int col = (q < 4) ? q * 4 : 16 + (q - 4) * 4;
            Xs[r][col + 0] = v.x; Xs[r][col + 1] = v.y;
            Xs[r][col + 2] = v.z; Xs[r][col + 3] = v.w;
        }
        __syncthreads();
        #pragma unroll
        for (int w2 = 0; w2 < 16; w2++) {
            float xlo = Xs[tid][w2], xhi = Xs[tid][16 + w2];
            float xp = xlo + xhi, xm = xlo - xhi;
            ull xpp = pk2(xp, xp), xmp = pk2(xm, xm);
            const ulonglong2* tw = (const ulonglong2*)&TWA[c0 + w2][0];
            #pragma unroll
            for (int k4 = 0; k4 < 8; k4++) {
                ulonglong2 tp = tw[k4];
                fma2(acc[2 * k4],     xpp, tp.x);   // even ky <- x+ fold
                fma2(acc[2 * k4 + 1], xmp, tp.y);   // odd  ky <- x- fold
            }
        }
    }

    #pragma unroll
    for (int k = 0; k < 16; k++) Fw[k][tid] = acc[k];
    __syncthreads();

    // Phase B: Xf[kx,ky] = sum_{h<64} (F[h] +/- F[h+64]) e^{-2pi i kx h/128}
    int ky = tid & 15, kxg = tid >> 4;
    ull accB[4] = {0, 0, 0, 0}, accC[4] = {0, 0, 0, 0};
    int kxv[4], idx[4];
    #pragma unroll
    for (int j = 0; j < 4; j++) {
        int kxIdx = kxg * 4 + j;
        kxv[j] = (kxIdx < 16) ? kxIdx : (96 + kxIdx);  // parity(kxv) == parity(j)
        idx[j] = 0;
    }
    for (int h = 0; h < 64; h++) {
        ull a = Fw[ky][h], b = Fw[ky][h + 64];
        ull p = add2(a, b), m = sub2(a, b);
        float pr, pi, mr, mi;
        upk2(p, pr, pi); upk2(m, mr, mi);
        ull prr = pk2(pr, pr), pii = pk2(pi, pi);
        ull mrr = pk2(mr, mr), mii = pk2(mi, mi);
        #pragma unroll
        for (int j = 0; j < 4; j++) {
            ulonglong2 e = *(const ulonglong2*)&TWB[idx[j]][0];
            if (j & 1) { fma2(accB[j], mrr, e.x); fma2(accC[j], mii, e.y); }
            else       { fma2(accB[j], prr, e.x); fma2(accC[j], pii, e.y); }
            idx[j] = (idx[j] + kxv[j]) & 127;
        }
    }
    int b = blockIdx.x >> 6, t = blockIdx.x & 63;
    #pragma unroll
    for (int j = 0; j < 4; j++) {
        int m = (kxg * 4 + j) * 16 + ky;
        ull r = add2(accB[j], accC[j]);
        float re, im; upk2(r, re, im);
        g_Xf[m * 1024 + t * 16 + b] = make_float2(re, im);
    }
}

// ---------------------------------------------------------------------------
// K2: mode mixing. grid = 512 modes, 256 threads, dynamic SMEM 91136B.
// ---------------------------------------------------------------------------
__global__ void __launch_bounds__(256) k_modes() {
    extern __shared__ __align__(16) char sm2[];
    ulonglong2* Wsp = (ulonglong2*)sm2;                          // [64 t][65]
    ulonglong2* Xsm = (ulonglong2*)(sm2 + 64 * 65 * 16);         // [64 t][16 b]
    ull*        Ys2 = (ull*)(sm2 + 64 * 65 * 16 + 64 * 16 * 16); // [1024]

    int m = blockIdx.x, tid = threadIdx.x;

    #pragma unroll
    for (int p = 0; p < 16; p++) {
        int i = tid + p * 256;                 // i = c*64 + t
        float2 w = g_W[(size_t)m * 4096 + i];
        Wsp[(i & 63) * 65 + (i >> 6)] = make_ulonglong2(pk2(w.x, w.x), pk2(w.y, w.y));
    }
    #pragma unroll
    for (int p = 0; p < 4; p++) {
        int i = tid + p * 256;                 // i = t*16 + b
        float2 x = g_Xf[m * 1024 + i];
        Xsm[i] = make_ulonglong2(pk2(x.x, x.y), pk2(-x.y, x.x));
    }
    __syncthreads();

    int b = tid >> 4, cf = tid & 15;
    ull acc[4] = {0, 0, 0, 0};
    for (int t = 0; t < 64; t++) {
        ulonglong2 xv = Xsm[t * 16 + b];
        #pragma unroll
        for (int j = 0; j < 4; j++) {
            ulonglong2 wv = Wsp[t * 65 + j * 16 + cf];
            fma2(acc[j], wv.x, xv.x);
            fma2(acc[j], wv.y, xv.y);
        }
    }
    #pragma unroll
    for (int j = 0; j < 4; j++) Ys2[b * 64 + j * 16 + cf] = acc[j];
    __syncthreads();
    #pragma unroll
    for (int p = 0; p < 4; p++) {
        int i = tid + p * 256;
        *(ull*)&g_Y[(size_t)m * 1024 + i] = Ys2[i];
    }
}

// ---------------------------------------------------------------------------
// K3: inverse. grid = B*C = 1024 blocks, 512 threads (occupancy/ILP fix).
// Radix-2 fold in kx parity (phase A) and w (phase B).
// ---------------------------------------------------------------------------
__global__ void __launch_bounds__(512) k_inverse(float* __restrict__ out) {
    __shared__ __align__(16) ull TWI[128][2];       // (c,s),(-s,c) — 2KB
    __shared__ ull Ysm[512];                        // 4KB
    __shared__ __align__(16) ulonglong2 ZZ[64][17]; // [(zr_h,zr_h64),(zi_h,zi_h64)]

    int tid = threadIdx.x;
    if (tid < 128) {
        float s, c; sincosf(PI2_OVER_128 * (float)tid, &s, &c);
        TWI[tid][0] = pk2(c, s);
        TWI[tid][1] = pk2(-s, c);
    }
    int off = blockIdx.x;   // b*64 + c
    Ysm[tid] = *(const ull*)&g_Y[(size_t)tid * 1024 + off];
    __syncthreads();

    // Phase A: Z[h] = Se+So, Z[h+64] = Se-So. Thread handles h in {hq, hq+32}.
    {
        int ky = tid & 15, hq = tid >> 4;          // hq in 0..31
        ull Se[2] = {0, 0}, So[2] = {0, 0};
        int hh[2] = {hq, hq + 32};
        int idx[2] = {0, 0};

        #pragma unroll
        for (int kxI = 0; kxI < 16; kxI++) {       // kx = kxI
            float yr, yi; upk2(Ysm[kxI * 16 + ky], yr, yi);
            ull yrr = pk2(yr, yr), yii = pk2(yi, yi);
            #pragma unroll
            for (int u = 0; u < 2; u++) {
                ulonglong2 e = *(const ulonglong2*)&TWI[idx[u]][0];
                if (kxI & 1) { fma2(So[u], yrr, e.x); fma2(So[u], yii, e.y); }
                else         { fma2(Se[u], yrr, e.x); fma2(Se[u], yii, e.y); }
                idx[u] = (idx[u] + hh[u]) & 127;
            }
        }
        #pragma unroll
        for (int u = 0; u < 2; u++) idx[u] = (112 * hh[u]) & 127;
        #pragma unroll
        for (int kxI = 16; kxI < 32; kxI++) {      // kx = 96+kxI, same parity
            float yr, yi; upk2(Ysm[kxI * 16 + ky], yr, yi);
            ull yrr = pk2(yr, yr), yii = pk2(yi, yi);
            #pragma unroll
            for (int u = 0; u < 2; u++) {
                ulonglong2 e = *(const ulonglong2*)&TWI[idx[u]][0];
                if (kxI & 1) { fma2(So[u], yrr, e.x); fma2(So[u], yii, e.y); }
                else         { fma2(Se[u], yrr, e.x); fma2(Se[u], yii, e.y); }
                idx[u] = (idx[u] + hh[u]) & 127;
            }
        }
        #pragma unroll
        for (int u = 0; u < 2; u++) {
            ull zp = add2(Se[u], So[u]);   // h = hh[u]
            ull zm = sub2(Se[u], So[u]);   // h = hh[u] + 64
            float pr, pi, mr, mi;
            upk2(zp, pr, pi); upk2(zm, mr, mi);
            ZZ[hh[u]][ky] = make_ulonglong2(pk2(pr, mr), pk2(pi, mi));
        }
    }
    __syncthreads();

    // Phase B: out[r,wl] = accE+accO, out[r,wl+64] = accE-accO (ky parity fold).
    // 8 rows per thread -> 16 ull accumulators (32 regs).
    int wl = tid & 63, rg = tid >> 6;      // rows r = rg*8 + i
    ull accE[8], accO[8];
    #pragma unroll
    for (int i = 0; i < 8; i++) {
        accE[i] = ZZ[rg * 8 + i][0].x;     // ky=0: Re(Z0), weight 1
        accO[i] = 0;
    }
    #pragma unroll
    for (int k = 1; k < 16; k++) {
        float c, s; upk2(TWI[(k * wl) & 127][0], c, s);
        ull tcp = pk2(2.f * c, 2.f * c);
        ull tsp = pk2(-2.f * s, -2.f * s);
        if (k & 1) {
            #pragma unroll
            for (int i = 0; i < 8; i++) {
                ulonglong2 zz = ZZ[rg * 8 + i][k];
                fma2(accO[i], zz.x, tcp);
                fma2(accO[i], zz.y, tsp);
            }
        } else {
            #pragma unroll
            for (int i = 0; i < 8; i++) {
                ulonglong2 zz = ZZ[rg * 8 + i][k];
                fma2(accE[i], zz.x, tcp);
                fma2(accE[i], zz.y, tsp);
            }
        }
    }
    float* op = out + (size_t)blockIdx.x * 16384;
    #pragma unroll
    for (int i = 0; i < 8; i++) {
        int r = rg * 8 + i;
        ull olo = add2(accE[i], accO[i]);   // w = wl
        ull ohi = sub2(accE[i], accO[i]);   // w = wl + 64
        float a0, a1, b0, b1;
        upk2(olo, a0, a1);                  // (h=r, h=r+64)
        upk2(ohi, b0, b1);
        op[r * 128 + wl]             = a0;
        op[(r + 64) * 128 + wl]      = a1;
        op[r * 128 + wl + 64]        = b0;
        op[(r + 64) * 128 + wl + 64] = b1;
    }
}

// ---------------------------------------------------------------------------
extern "C" void kernel_launch(void* const* d_in, const int* in_sizes, int n_in,
                              void* d_out, int out_size) {
    const float* X   = (const float*)d_in[0];
    const float* w0r = (const float*)d_in[1];
    const float* w0i = (const float*)d_in[2];
    const float* w1r = (const float*)d_in[3];
    const float* w1i = (const float*)d_in[4];
    float* out = (float*)d_out;

    static bool attr_done = false;
    if (!attr_done) {
        cudaFuncSetAttribute(k_modes, cudaFuncAttributeMaxDynamicSharedMemorySize,
                             91136);
        attr_done = true;
    }

    k_fwd_tr<<<3072, 128>>>(X, w0r, w0i, w1r, w1i);
    k_modes<<<512, 256, 91136>>>();
    k_inverse<<<1024, 512>>>(out);
}

// round 7
// speedup vs baseline: 1.0121x; 1.0121x over previous
#include <cuda_runtime.h>
#include <cstdint>

// FactorizedSpectralConv on GB300 — radix-2 folded direct DFTs.
// k_forward phase A uses compile-time immediate twiddles (FFMA-imm, rt=1).
// B=16, C=64, H=W=128, M0=M1=16.

typedef unsigned long long ull;
#define PI2_OVER_128 0.04908738521234051935f  // 2*pi/128
#define SGN2 0x8000000080000000ULL

// Scratch (device globals; allocation-free rule)
__device__ float2 g_Xf[512 * 1024];   // [m][t*16+b], 4 MB
__device__ float2 g_Y [512 * 1024];   // [m][b*64+c], 4 MB
__device__ float2 g_W [512 * 4096];   // [m][c*64+t], 16 MB (transposed weights)

__device__ __forceinline__ ull pk2(float x, float y) {
    ull r; asm("mov.b64 %0,{%1,%2};" : "=l"(r) : "f"(x), "f"(y)); return r;
}
__device__ __forceinline__ void upk2(ull v, float& x, float& y) {
    asm("mov.b64 {%0,%1},%2;" : "=f"(x), "=f"(y) : "l"(v));
}
__device__ __forceinline__ void fma2(ull& d, ull a, ull b) {
    asm("fma.rn.f32x2 %0,%1,%2,%0;" : "+l"(d) : "l"(a), "l"(b));
}
__device__ __forceinline__ ull add2(ull a, ull b) {
    ull d; asm("add.rn.f32x2 %0,%1,%2;" : "=l"(d) : "l"(a), "l"(b)); return d;
}
__device__ __forceinline__ ull sub2(ull a, ull b) {
    return add2(a, b ^ SGN2);
}

// ---- compile-time trig (double Taylor, |x| <= pi, err ~1e-11) ----
constexpr double PI_D = 3.14159265358979323846264338327950288;
__host__ __device__ constexpr double tsin_(double x) {
    double t = x, s = x, x2 = x * x;
    for (int i = 1; i <= 12; i++) { t *= -x2 / double((2 * i) * (2 * i + 1)); s += t; }
    return s;
}
__host__ __device__ constexpr double tcos_(double x) {
    double t = 1.0, s = 1.0, x2 = x * x;
    for (int i = 1; i <= 12; i++) { t *= -x2 / double((2 * i - 1) * (2 * i)); s += t; }
    return s;
}
__host__ __device__ constexpr float TWC(int w, int k) {   // cos/16384
    int n = (w * k) & 127;
    double x = (2.0 * PI_D * n) / 128.0;
    if (n > 64) x -= 2.0 * PI_D;
    return (float)(tcos_(x) / 16384.0);
}
__host__ __device__ constexpr float TWS(int w, int k) {   // -sin/16384
    int n = (w * k) & 127;
    double x = (2.0 * PI_D * n) / 128.0;
    if (n > 64) x -= 2.0 * PI_D;
    return (float)(-tsin_(x) / 16384.0);
}

// ---- templated phase-A MAC ladder: all twiddles become FFMA immediates ----
template <int W, int K = 0>
__device__ __forceinline__ void rowA(float xp, float xm, float* ar, float* ai) {
    if constexpr (K < 16) {
        constexpr float c = TWC(W, K);
        constexpr float s = TWS(W, K);
        float x = (K & 1) ? xm : xp;   // even ky <- x[w]+x[w+64], odd <- diff
        ar[K] = fmaf(x, c, ar[K]);
        ai[K] = fmaf(x, s, ai[K]);
        rowA<W, K + 1>(xp, xm, ar, ai);
    }
}
template <int C0, int W2 = 0>
__device__ __forceinline__ void chunkA(const float2 (*Xs2)[17], int tid,
                                       float* ar, float* ai) {
    if constexpr (W2 < 16) {
        float2 xv = Xs2[tid][W2];      // (x[w], x[w+64])
        rowA<C0 + W2>(xv.x + xv.y, xv.x - xv.y, ar, ai);
        chunkA<C0, W2 + 1>(Xs2, tid, ar, ai);
    }
}

// ---------------------------------------------------------------------------
// K0: weight transpose  w[c][t][kx0][ky] (stride-256 cols) -> g_W[m][c*64+t]
// ---------------------------------------------------------------------------
__global__ void __launch_bounds__(256) k_transpose(
    const float* __restrict__ w0r, const float* __restrict__ w0i,
    const float* __restrict__ w1r, const float* __restrict__ w1i) {
    __shared__ float Tr[32][33], Ti[32][33];
    int bid = blockIdx.x;
    int arr = bid >> 10;
    int tix = bid & 1023;
    int ctTile = tix >> 3, mTile = tix & 7;
    const float* Sr = arr ? w1r : w0r;
    const float* Si = arr ? w1i : w0i;
    int tx = threadIdx.x & 31, ty = threadIdx.x >> 5;
    #pragma unroll
    for (int yy = 0; yy < 4; yy++) {
        int r = ty + yy * 8;
        int row = ctTile * 32 + r, col = mTile * 32 + tx;
        Tr[r][tx] = Sr[row * 256 + col];
        Ti[r][tx] = Si[row * 256 + col];
    }
    __syncthreads();
    #pragma unroll
    for (int yy = 0; yy < 4; yy++) {
        int r = ty + yy * 8;
        int m = arr * 256 + mTile * 32 + r;
        int ct = ctTile * 32 + tx;
        g_W[(size_t)m * 4096 + ct] = make_float2(Tr[tx][r], Ti[tx][r]);
    }
}

// ---------------------------------------------------------------------------
// K1: forward. grid = B*C = 1024 blocks, 128 threads (thread = h row).
// Phase A: immediate-twiddle scalar FFMA. Phase B: LDS twiddle recurrence.
// ---------------------------------------------------------------------------
__global__ void __launch_bounds__(128) k_forward(const float* __restrict__ X) {
    __shared__ __align__(16) ull TWB[128][2];   // (c,-s),(s,c) — 2KB
    __shared__ float2 Xs2[128][17];             // (x[w], x[w+64]) pairs — 17.4KB
    __shared__ ull    Fw[16][129];              // packed F[ky][h] — 16.5KB

    int tid = threadIdx.x;
    {
        float s, c; sincosf(PI2_OVER_128 * (float)tid, &s, &c);
        TWB[tid][0] = pk2(c, -s);
        TWB[tid][1] = pk2(s, c);
    }

    const float* Xp = X + (size_t)blockIdx.x * 16384;

    // Phase A: F[h,ky] = sum_{w<64} (X[w] +/- X[w+64]) e^{-2pi i ky w/128}
    float ar[16], ai[16];
    #pragma unroll
    for (int k = 0; k < 16; k++) { ar[k] = 0.f; ai[k] = 0.f; }

    #pragma unroll 1
    for (int c0 = 0; c0 < 64; c0 += 16) {
        __syncthreads();
        #pragma unroll
        for (int p = 0; p < 8; p++) {
            int i = p * 128 + tid;
            int r = i >> 3, q = i & 7;
            const float* src = (q < 4) ? (Xp + r * 128 + c0 + q * 4)
                                       : (Xp + r * 128 + c0 + 64 + (q - 4) * 4);
            float4 v = *(const float4*)src;
            if (q < 4) {
                Xs2[r][q * 4 + 0].x = v.x; Xs2[r][q * 4 + 1].x = v.y;
                Xs2[r][q * 4 + 2].x = v.z; Xs2[r][q * 4 + 3].x = v.w;
            } else {
                Xs2[r][(q - 4) * 4 + 0].y = v.x; Xs2[r][(q - 4) * 4 + 1].y = v.y;
                Xs2[r][(q - 4) * 4 + 2].y = v.z; Xs2[r][(q - 4) * 4 + 3].y = v.w;
            }
        }
        __syncthreads();
        switch (c0) {
            case 0:  chunkA<0 >(Xs2, tid, ar, ai); break;
            case 16: chunkA<16>(Xs2, tid, ar, ai); break;
            case 32: chunkA<32>(Xs2, tid, ar, ai); break;
            default: chunkA<48>(Xs2, tid, ar, ai); break;
        }
    }

    #pragma unroll
    for (int k = 0; k < 16; k++) Fw[k][tid] = pk2(ar[k], ai[k]);
    __syncthreads();

    // Phase B: Xf[kx,ky] = sum_{h<64} (F[h] +/- F[h+64]) e^{-2pi i kx h/128}
    int ky = tid & 15, kxg = tid >> 4;
    ull accB[4] = {0, 0, 0, 0}, accC[4] = {0, 0, 0, 0};
    int kxv[4], idx[4];
    #pragma unroll
    for (int j = 0; j < 4; j++) {
        int kxIdx = kxg * 4 + j;
        kxv[j] = (kxIdx < 16) ? kxIdx : (96 + kxIdx);  // parity(kxv)==parity(j)
        idx[j] = 0;
    }
    for (int h = 0; h < 64; h++) {
        ull a = Fw[ky][h], b = Fw[ky][h + 64];
        ull p = add2(a, b), m = sub2(a, b);
        float pr, pi, mr, mi;
        upk2(p, pr, pi); upk2(m, mr, mi);
        ull prr = pk2(pr, pr), pii = pk2(pi, pi);
        ull mrr = pk2(mr, mr), mii = pk2(mi, mi);
        #pragma unroll
        for (int j = 0; j < 4; j++) {
            ulonglong2 e = *(const ulonglong2*)&TWB[idx[j]][0];
            if (j & 1) { fma2(accB[j], mrr, e.x); fma2(accC[j], mii, e.y); }
            else       { fma2(accB[j], prr, e.x); fma2(accC[j], pii, e.y); }
            idx[j] = (idx[j] + kxv[j]) & 127;
        }
    }
    int b = blockIdx.x >> 6, t = blockIdx.x & 63;
    #pragma unroll
    for (int j = 0; j < 4; j++) {
        int m = (kxg * 4 + j) * 16 + ky;
        ull r = add2(accB[j], accC[j]);
        float re, im; upk2(r, re, im);
        g_Xf[m * 1024 + t * 16 + b] = make_float2(re, im);
    }
}

// ---------------------------------------------------------------------------
// K2: mode mixing. grid = 512 modes, 256 threads, dynamic SMEM 91136B.
// ---------------------------------------------------------------------------
__global__ void __launch_bounds__(256) k_modes() {
    extern __shared__ __align__(16) char sm2[];
    ulonglong2* Wsp = (ulonglong2*)sm2;                          // [64 t][65]
    ulonglong2* Xsm = (ulonglong2*)(sm2 + 64 * 65 * 16);         // [64 t][16 b]
    ull*        Ys2 = (ull*)(sm2 + 64 * 65 * 16 + 64 * 16 * 16); // [1024]

    int m = blockIdx.x, tid = threadIdx.x;

    #pragma unroll
    for (int p = 0; p < 16; p++) {
        int i = tid + p * 256;                 // i = c*64 + t
        float2 w = g_W[(size_t)m * 4096 + i];
        Wsp[(i & 63) * 65 + (i >> 6)] = make_ulonglong2(pk2(w.x, w.x), pk2(w.y, w.y));
    }
    #pragma unroll
    for (int p = 0; p < 4; p++) {
        int i = tid + p * 256;                 // i = t*16 + b
        float2 x = g_Xf[m * 1024 + i];
        Xsm[i] = make_ulonglong2(pk2(x.x, x.y), pk2(-x.y, x.x));
    }
    __syncthreads();

    int b = tid >> 4, cf = tid & 15;
    ull acc[4] = {0, 0, 0, 0};
    for (int t = 0; t < 64; t++) {
        ulonglong2 xv = Xsm[t * 16 + b];
        #pragma unroll
        for (int j = 0; j < 4; j++) {
            ulonglong2 wv = Wsp[t * 65 + j * 16 + cf];
            fma2(acc[j], wv.x, xv.x);
            fma2(acc[j], wv.y, xv.y);
        }
    }
    #pragma unroll
    for (int j = 0; j < 4; j++) Ys2[b * 64 + j * 16 + cf] = acc[j];
    __syncthreads();
    #pragma unroll
    for (int p = 0; p < 4; p++) {
        int i = tid + p * 256;
        *(ull*)&g_Y[(size_t)m * 1024 + i] = Ys2[i];
    }
}

// ---------------------------------------------------------------------------
// K3: inverse. grid = B*C = 1024 blocks, 512 threads.
// Radix-2 fold in kx parity (phase A) and w (phase B).
// ---------------------------------------------------------------------------
__global__ void __launch_bounds__(512) k_inverse(float* __restrict__ out) {
    __shared__ __align__(16) ull TWI[128][2];       // (c,s),(-s,c) — 2KB
    __shared__ ull Ysm[512];                        // 4KB
    __shared__ __align__(16) ulonglong2 ZZ[64][17]; // [(zr_h,zr_h64),(zi_h,zi_h64)]

    int tid = threadIdx.x;
    if (tid < 128) {
        float s, c; sincosf(PI2_OVER_128 * (float)tid, &s, &c);
        TWI[tid][0] = pk2(c, s);
        TWI[tid][1] = pk2(-s, c);
    }
    int off = blockIdx.x;   // b*64 + c
    Ysm[tid] = *(const ull*)&g_Y[(size_t)tid * 1024 + off];
    __syncthreads();

    // Phase A: Z[h] = Se+So, Z[h+64] = Se-So. Thread handles h in {hq, hq+32}.
    {
        int ky = tid & 15, hq = tid >> 4;          // hq in 0..31
        ull Se[2] = {0, 0}, So[2] = {0, 0};
        int hh[2] = {hq, hq + 32};
        int idx[2] = {0, 0};

        #pragma unroll
        for (int kxI = 0; kxI < 16; kxI++) {       // kx = kxI
            float yr, yi; upk2(Ysm[kxI * 16 + ky], yr, yi);
            ull yrr = pk2(yr, yr), yii = pk2(yi, yi);
            #pragma unroll
            for (int u = 0; u < 2; u++) {
                ulonglong2 e = *(const ulonglong2*)&TWI[idx[u]][0];
                if (kxI & 1) { fma2(So[u], yrr, e.x); fma2(So[u], yii, e.y); }
                else         { fma2(Se[u], yrr, e.x); fma2(Se[u], yii, e.y); }
                idx[u] = (idx[u] + hh[u]) & 127;
            }
        }
        #pragma unroll
        for (int u = 0; u < 2; u++) idx[u] = (112 * hh[u]) & 127;
        #pragma unroll
        for (int kxI = 16; kxI < 32; kxI++) {      // kx = 96+kxI, same parity
            float yr, yi; upk2(Ysm[kxI * 16 + ky], yr, yi);
            ull yrr = pk2(yr, yr), yii = pk2(yi, yi);
            #pragma unroll
            for (int u = 0; u < 2; u++) {
                ulonglong2 e = *(const ulonglong2*)&TWI[idx[u]][0];
                if (kxI & 1) { fma2(So[u], yrr, e.x); fma2(So[u], yii, e.y); }
                else         { fma2(Se[u], yrr, e.x); fma2(Se[u], yii, e.y); }
                idx[u] = (idx[u] + hh[u]) & 127;
            }
        }
        #pragma unroll
        for (int u = 0; u < 2; u++) {
            ull zp = add2(Se[u], So[u]);   // h = hh[u]
            ull zm = sub2(Se[u], So[u]);   // h = hh[u] + 64
            float pr, pi, mr, mi;
            upk2(zp, pr, pi); upk2(zm, mr, mi);
            ZZ[hh[u]][ky] = make_ulonglong2(pk2(pr, mr), pk2(pi, mi));
        }
    }
    __syncthreads();

    // Phase B: out[r,wl] = accE+accO, out[r,wl+64] = accE-accO (ky parity fold).
    int wl = tid & 63, rg = tid >> 6;      // rows r = rg*8 + i
    ull accE[8], accO[8];
    #pragma unroll
    for (int i = 0; i < 8; i++) {
        accE[i] = ZZ[rg * 8 + i][0].x;     // ky=0: Re(Z0), weight 1
        accO[i] = 0;
    }
    #pragma unroll
    for (int k = 1; k < 16; k++) {
        float c, s; upk2(TWI[(k * wl) & 127][0], c, s);
        ull tcp = pk2(2.f * c, 2.f * c);
        ull tsp = pk2(-2.f * s, -2.f * s);
        if (k & 1) {
            #pragma unroll
            for (int i = 0; i < 8; i++) {
                ulonglong2 zz = ZZ[rg * 8 + i][k];
                fma2(accO[i], zz.x, tcp);
                fma2(accO[i], zz.y, tsp);
            }
        } else {
            #pragma unroll
            for (int i = 0; i < 8; i++) {
                ulonglong2 zz = ZZ[rg * 8 + i][k];
                fma2(accE[i], zz.x, tcp);
                fma2(accE[i], zz.y, tsp);
            }
        }
    }
    float* op = out + (size_t)blockIdx.x * 16384;
    #pragma unroll
    for (int i = 0; i < 8; i++) {
        int r = rg * 8 + i;
        ull olo = add2(accE[i], accO[i]);   // w = wl
        ull ohi = sub2(accE[i], accO[i]);   // w = wl + 64
        float a0, a1, b0, b1;
        upk2(olo, a0, a1);                  // (h=r, h=r+64)
        upk2(ohi, b0, b1);
        op[r * 128 + wl]             = a0;
        op[(r + 64) * 128 + wl]      = a1;
        op[r * 128 + wl + 64]        = b0;
        op[(r + 64) * 128 + wl + 64] = b1;
    }
}

// ---------------------------------------------------------------------------
extern "C" void kernel_launch(void* const* d_in, const int* in_sizes, int n_in,
                              void* d_out, int out_size) {
    const float* X   = (const float*)d_in[0];
    const float* w0r = (const float*)d_in[1];
    const float* w0i = (const float*)d_in[2];
    const float* w1r = (const float*)d_in[3];
    const float* w1i = (const float*)d_in[4];
    float* out = (float*)d_out;

    static bool attr_done = false;
    if (!attr_done) {
        cudaFuncSetAttribute(k_modes, cudaFuncAttributeMaxDynamicSharedMemorySize,
                             91136);
        attr_done = true;
    }

    k_transpose<<<2048, 256>>>(w0r, w0i, w1r, w1i);
    k_forward<<<1024, 128>>>(X);
    k_modes<<<512, 256, 91136>>>();
    k_inverse<<<1024, 512>>>(out);
}

// round 8
// speedup vs baseline: 1.2209x; 1.2063x over previous
#include <cuda_runtime.h>
#include <cstdint>

// FactorizedSpectralConv on GB300 — radix-2 folded direct DFTs.
// Residency-tuned: 50% occ targets on forward/inverse; broadcast weights in modes.
// B=16, C=64, H=W=128, M0=M1=16.

typedef unsigned long long ull;
#define PI2_OVER_128 0.04908738521234051935f  // 2*pi/128
#define SGN2 0x8000000080000000ULL

// Scratch (device globals; allocation-free rule)
__device__ float2 g_Xf[512 * 1024];   // [m][t*16+b], 4 MB
__device__ float2 g_Y [512 * 1024];   // [m][b*64+c], 4 MB
__device__ float2 g_W [512 * 4096];   // [m][c*64+t], 16 MB (transposed weights)

__device__ __forceinline__ ull pk2(float x, float y) {
    ull r; asm("mov.b64 %0,{%1,%2};" : "=l"(r) : "f"(x), "f"(y)); return r;
}
__device__ __forceinline__ void upk2(ull v, float& x, float& y) {
    asm("mov.b64 {%0,%1},%2;" : "=f"(x), "=f"(y) : "l"(v));
}
__device__ __forceinline__ void fma2(ull& d, ull a, ull b) {
    asm("fma.rn.f32x2 %0,%1,%2,%0;" : "+l"(d) : "l"(a), "l"(b));
}
__device__ __forceinline__ ull add2(ull a, ull b) {
    ull d; asm("add.rn.f32x2 %0,%1,%2;" : "=l"(d) : "l"(a), "l"(b)); return d;
}
__device__ __forceinline__ ull sub2(ull a, ull b) {
    return add2(a, b ^ SGN2);
}

// ---- compile-time trig (double Taylor, |x| <= pi, err ~1e-11) ----
constexpr double PI_D = 3.14159265358979323846264338327950288;
__host__ __device__ constexpr double tsin_(double x) {
    double t = x, s = x, x2 = x * x;
    for (int i = 1; i <= 12; i++) { t *= -x2 / double((2 * i) * (2 * i + 1)); s += t; }
    return s;
}
__host__ __device__ constexpr double tcos_(double x) {
    double t = 1.0, s = 1.0, x2 = x * x;
    for (int i = 1; i <= 12; i++) { t *= -x2 / double((2 * i - 1) * (2 * i)); s += t; }
    return s;
}
__host__ __device__ constexpr float TWC(int w, int k) {   // cos/16384
    int n = (w * k) & 127;
    double x = (2.0 * PI_D * n) / 128.0;
    if (n > 64) x -= 2.0 * PI_D;
    return (float)(tcos_(x) / 16384.0);
}
__host__ __device__ constexpr float TWS(int w, int k) {   // -sin/16384
    int n = (w * k) & 127;
    double x = (2.0 * PI_D * n) / 128.0;
    if (n > 64) x -= 2.0 * PI_D;
    return (float)(-tsin_(x) / 16384.0);
}

// ---- templated phase-A MAC ladder: all twiddles become FFMA immediates ----
template <int W, int K = 0>
__device__ __forceinline__ void rowA(float xp, float xm, float* ar, float* ai) {
    if constexpr (K < 16) {
        constexpr float c = TWC(W, K);
        constexpr float s = TWS(W, K);
        float x = (K & 1) ? xm : xp;   // even ky <- x[w]+x[w+64], odd <- diff
        ar[K] = fmaf(x, c, ar[K]);
        ai[K] = fmaf(x, s, ai[K]);
        rowA<W, K + 1>(xp, xm, ar, ai);
    }
}
template <int C0, int W2 = 0>
__device__ __forceinline__ void chunkA(const float2 (*Xs2)[17], int tid,
                                       float* ar, float* ai) {
    if constexpr (W2 < 16) {
        float2 xv = Xs2[tid][W2];      // (x[w], x[w+64])
        rowA<C0 + W2>(xv.x + xv.y, xv.x - xv.y, ar, ai);
        chunkA<C0, W2 + 1>(Xs2, tid, ar, ai);
    }
}

// ---------------------------------------------------------------------------
// K0: weight transpose  w[c][t][kx0][ky] (stride-256 cols) -> g_W[m][c*64+t]
// ---------------------------------------------------------------------------
__global__ void __launch_bounds__(256) k_transpose(
    const float* __restrict__ w0r, const float* __restrict__ w0i,
    const float* __restrict__ w1r, const float* __restrict__ w1i) {
    __shared__ float Tr[32][33], Ti[32][33];
    int bid = blockIdx.x;
    int arr = bid >> 10;
    int tix = bid & 1023;
    int ctTile = tix >> 3, mTile = tix & 7;
    const float* Sr = arr ? w1r : w0r;
    const float* Si = arr ? w1i : w0i;
    int tx = threadIdx.x & 31, ty = threadIdx.x >> 5;
    #pragma unroll
    for (int yy = 0; yy < 4; yy++) {
        int r = ty + yy * 8;
        int row = ctTile * 32 + r, col = mTile * 32 + tx;
        Tr[r][tx] = Sr[row * 256 + col];
        Ti[r][tx] = Si[row * 256 + col];
    }
    __syncthreads();
    #pragma unroll
    for (int yy = 0; yy < 4; yy++) {
        int r = ty + yy * 8;
        int m = arr * 256 + mTile * 32 + r;
        int ct = ctTile * 32 + tx;
        g_W[(size_t)m * 4096 + ct] = make_float2(Tr[tx][r], Ti[tx][r]);
    }
}

// ---------------------------------------------------------------------------
// K1: forward. grid = 1024 blocks, 128 threads, Xs2/Fw smem overlay, 64 regs.
// ---------------------------------------------------------------------------
__global__ void __launch_bounds__(128, 8) k_forward(const float* __restrict__ X) {
    __shared__ __align__(16) ull TWB[128][2];   // (c,-s),(s,c) — 2KB
    __shared__ __align__(16) char u_smem[17408];  // Xs2 (17408B) / Fw (16512B)
    float2 (*Xs2)[17] = (float2(*)[17])u_smem;
    ull    (*Fw)[129] = (ull(*)[129])u_smem;

    int tid = threadIdx.x;
    {
        float s, c; sincosf(PI2_OVER_128 * (float)tid, &s, &c);
        TWB[tid][0] = pk2(c, -s);
        TWB[tid][1] = pk2(s, c);
    }

    const float* Xp = X + (size_t)blockIdx.x * 16384;

    // Phase A: F[h,ky] = sum_{w<64} (X[w] +/- X[w+64]) e^{-2pi i ky w/128}
    float ar[16], ai[16];
    #pragma unroll
    for (int k = 0; k < 16; k++) { ar[k] = 0.f; ai[k] = 0.f; }

    #pragma unroll 1
    for (int c0 = 0; c0 < 64; c0 += 16) {
        __syncthreads();
        #pragma unroll
        for (int p = 0; p < 8; p++) {
            int i = p * 128 + tid;
            int r = i >> 3, q = i & 7;
            const float* src = (q < 4) ? (Xp + r * 128 + c0 + q * 4)
                                       : (Xp + r * 128 + c0 + 64 + (q - 4) * 4);
            float4 v = *(const float4*)src;
            if (q < 4) {
                Xs2[r][q * 4 + 0].x = v.x; Xs2[r][q * 4 + 1].x = v.y;
                Xs2[r][q * 4 + 2].x = v.z; Xs2[r][q * 4 + 3].x = v.w;
            } else {
                Xs2[r][(q - 4) * 4 + 0].y = v.x; Xs2[r][(q - 4) * 4 + 1].y = v.y;
                Xs2[r][(q - 4) * 4 + 2].y = v.z; Xs2[r][(q - 4) * 4 + 3].y = v.w;
            }
        }
        __syncthreads();
        switch (c0) {
            case 0:  chunkA<0 >(Xs2, tid, ar, ai); break;
            case 16: chunkA<16>(Xs2, tid, ar, ai); break;
            case 32: chunkA<32>(Xs2, tid, ar, ai); break;
            default: chunkA<48>(Xs2, tid, ar, ai); break;
        }
    }

    __syncthreads();   // all Xs2 reads done before Fw overlay writes
    #pragma unroll
    for (int k = 0; k < 16; k++) Fw[k][tid] = pk2(ar[k], ai[k]);
    __syncthreads();

    // Phase B: Xf[kx,ky] = sum_{h<64} (F[h] +/- F[h+64]) e^{-2pi i kx h/128}
    int ky = tid & 15, kxg = tid >> 4;
    ull accB[4] = {0, 0, 0, 0}, accC[4] = {0, 0, 0, 0};
    int kxv[4], idx[4];
    #pragma unroll
    for (int j = 0; j < 4; j++) {
        int kxIdx = kxg * 4 + j;
        kxv[j] = (kxIdx < 16) ? kxIdx : (96 + kxIdx);  // parity(kxv)==parity(j)
        idx[j] = 0;
    }
    for (int h = 0; h < 64; h++) {
        ull a = Fw[ky][h], b = Fw[ky][h + 64];
        ull p = add2(a, b), m = sub2(a, b);
        float pr, pi, mr, mi;
        upk2(p, pr, pi); upk2(m, mr, mi);
        ull prr = pk2(pr, pr), pii = pk2(pi, pi);
        ull mrr = pk2(mr, mr), mii = pk2(mi, mi);
        #pragma unroll
        for (int j = 0; j < 4; j++) {
            ulonglong2 e = *(const ulonglong2*)&TWB[idx[j]][0];
            if (j & 1) { fma2(accB[j], mrr, e.x); fma2(accC[j], mii, e.y); }
            else       { fma2(accB[j], prr, e.x); fma2(accC[j], pii, e.y); }
            idx[j] = (idx[j] + kxv[j]) & 127;
        }
    }
    int b = blockIdx.x >> 6, t = blockIdx.x & 63;
    #pragma unroll
    for (int j = 0; j < 4; j++) {
        int m = (kxg * 4 + j) * 16 + ky;
        ull r = add2(accB[j], accC[j]);
        float re, im; upk2(r, re, im);
        g_Xf[m * 1024 + t * 16 + b] = make_float2(re, im);
    }
}

// ---------------------------------------------------------------------------
// K2: mode mixing. grid = 512, 256 threads. b in lanes -> weights broadcast.
// ---------------------------------------------------------------------------
__global__ void __launch_bounds__(256) k_modes() {
    extern __shared__ __align__(16) char sm2[];
    ulonglong2* Wsp = (ulonglong2*)sm2;                          // [64 t][65] (c)
    ulonglong2* Xsm = (ulonglong2*)(sm2 + 64 * 65 * 16);         // [64 t][16 b]
    ull*        Ys2 = (ull*)(sm2 + 64 * 65 * 16 + 64 * 16 * 16); // [1024]

    int m = blockIdx.x, tid = threadIdx.x;

    #pragma unroll
    for (int p = 0; p < 16; p++) {
        int i = tid + p * 256;                 // i = c*64 + t
        float2 w = g_W[(size_t)m * 4096 + i];
        Wsp[(i & 63) * 65 + (i >> 6)] = make_ulonglong2(pk2(w.x, w.x), pk2(w.y, w.y));
    }
    #pragma unroll
    for (int p = 0; p < 4; p++) {
        int i = tid + p * 256;                 // i = t*16 + b
        float2 x = g_Xf[m * 1024 + i];
        Xsm[i] = make_ulonglong2(pk2(x.x, x.y), pk2(-x.y, x.x));
    }
    __syncthreads();

    // b in lanes: weight loads are warp-broadcast (2 distinct addrs/warp).
    int b = tid & 15, cq = tid >> 4;           // c = cq*4 + j
    ull acc[4] = {0, 0, 0, 0};
    for (int t = 0; t < 64; t++) {
        ulonglong2 xv = Xsm[t * 16 + b];
        #pragma unroll
        for (int j = 0; j < 4; j++) {
            ulonglong2 wv = Wsp[t * 65 + cq * 4 + j];
            fma2(acc[j], wv.x, xv.x);   // (yr,yi) += (wr,wr)*(xr,xi)
            fma2(acc[j], wv.y, xv.y);   //          + (wi,wi)*(-xi,xr)
        }
    }
    #pragma unroll
    for (int j = 0; j < 4; j++) Ys2[b * 64 + cq * 4 + j] = acc[j];
    __syncthreads();
    #pragma unroll
    for (int p = 0; p < 4; p++) {
        int i = tid + p * 256;
        *(ull*)&g_Y[(size_t)m * 1024 + i] = Ys2[i];
    }
}

// ---------------------------------------------------------------------------
// K3: inverse. grid = 1024 blocks, 256 threads, <=64 regs -> 4 blocks/SM.
// Radix-2 fold in kx parity (phase A) and w (phase B, two 8-row passes).
// ---------------------------------------------------------------------------
__global__ void __launch_bounds__(256, 4) k_inverse(float* __restrict__ out) {
    __shared__ __align__(16) ull TWI[128][2];       // (c,s),(-s,c) — 2KB
    __shared__ ull Ysm[512];                        // 4KB
    __shared__ __align__(16) ulonglong2 ZZ[64][17]; // [(zr_h,zr_h64),(zi_h,zi_h64)]

    int tid = threadIdx.x;
    if (tid < 128) {
        float s, c; sincosf(PI2_OVER_128 * (float)tid, &s, &c);
        TWI[tid][0] = pk2(c, s);
        TWI[tid][1] = pk2(-s, c);
    }
    int off = blockIdx.x;   // b*64 + c
    Ysm[tid]       = *(const ull*)&g_Y[(size_t)tid * 1024 + off];
    Ysm[tid + 256] = *(const ull*)&g_Y[(size_t)(tid + 256) * 1024 + off];
    __syncthreads();

    // Phase A: Z[h] = Se+So, Z[h+64] = Se-So. Thread: h in {hq, hq+16, hq+32, hq+48}.
    {
        int ky = tid & 15, hq = tid >> 4;          // hq in 0..15
        ull Se[4] = {0, 0, 0, 0}, So[4] = {0, 0, 0, 0};
        int idx[4] = {0, 0, 0, 0};

        #pragma unroll
        for (int kxI = 0; kxI < 16; kxI++) {       // kx = kxI
            float yr, yi; upk2(Ysm[kxI * 16 + ky], yr, yi);
            ull yrr = pk2(yr, yr), yii = pk2(yi, yi);
            #pragma unroll
            for (int u = 0; u < 4; u++) {
                ulonglong2 e = *(const ulonglong2*)&TWI[idx[u]][0];
                if (kxI & 1) { fma2(So[u], yrr, e.x); fma2(So[u], yii, e.y); }
                else         { fma2(Se[u], yrr, e.x); fma2(Se[u], yii, e.y); }
                idx[u] = (idx[u] + hq + 16 * u) & 127;
            }
        }
        #pragma unroll
        for (int u = 0; u < 4; u++) idx[u] = (112 * (hq + 16 * u)) & 127;
        #pragma unroll
        for (int kxI = 16; kxI < 32; kxI++) {      // kx = 96+kxI, same parity
            float yr, yi; upk2(Ysm[kxI * 16 + ky], yr, yi);
            ull yrr = pk2(yr, yr), yii = pk2(yi, yi);
            #pragma unroll
            for (int u = 0; u < 4; u++) {
                ulonglong2 e = *(const ulonglong2*)&TWI[idx[u]][0];
                if (kxI & 1) { fma2(So[u], yrr, e.x); fma2(So[u], yii, e.y); }
                else         { fma2(Se[u], yrr, e.x); fma2(Se[u], yii, e.y); }
                idx[u] = (idx[u] + hq + 16 * u) & 127;
            }
        }
        #pragma unroll
        for (int u = 0; u < 4; u++) {
            int r = hq + 16 * u;
            ull zp = add2(Se[u], So[u]);   // h = r
            ull zm = sub2(Se[u], So[u]);   // h = r + 64
            float pr, pi, mr, mi;
            upk2(zp, pr, pi); upk2(zm, mr, mi);
            ZZ[r][ky] = make_ulonglong2(pk2(pr, mr), pk2(pi, mi));
        }
    }
    __syncthreads();

    // Phase B: out[r,wl] = accE+accO, out[r,wl+64] = accE-accO (ky parity fold).
    // Two passes of 8 rows -> 16 ull accumulators, fits 64-reg budget.
    int wl = tid & 63, rg = tid >> 6;      // rg in 0..3
    float* op = out + (size_t)blockIdx.x * 16384;
    #pragma unroll 1
    for (int pass = 0; pass < 2; pass++) {
        int r0 = rg * 16 + pass * 8;
        ull accE[8], accO[8];
        #pragma unroll
        for (int i = 0; i < 8; i++) {
            accE[i] = ZZ[r0 + i][0].x;     // ky=0: Re(Z0), weight 1
            accO[i] = 0;
        }
        #pragma unroll
        for (int k = 1; k < 16; k++) {
            float c, s; upk2(TWI[(k * wl) & 127][0], c, s);
            ull tcp = pk2(2.f * c, 2.f * c);
            ull tsp = pk2(-2.f * s, -2.f * s);
            if (k & 1) {
                #pragma unroll
                for (int i = 0; i < 8; i++) {
                    ulonglong2 zz = ZZ[r0 + i][k];
                    fma2(accO[i], zz.x, tcp);
                    fma2(accO[i], zz.y, tsp);
                }
            } else {
                #pragma unroll
                for (int i = 0; i < 8; i++) {
                    ulonglong2 zz = ZZ[r0 + i][k];
                    fma2(accE[i], zz.x, tcp);
                    fma2(accE[i], zz.y, tsp);
                }
            }
        }
        #pragma unroll
        for (int i = 0; i < 8; i++) {
            int r = r0 + i;
            ull olo = add2(accE[i], accO[i]);   // w = wl
            ull ohi = sub2(accE[i], accO[i]);   // w = wl + 64
            float a0, a1, b0, b1;
            upk2(olo, a0, a1);                  // (h=r, h=r+64)
            upk2(ohi, b0, b1);
            op[r * 128 + wl]             = a0;
            op[(r + 64) * 128 + wl]      = a1;
            op[r * 128 + wl + 64]        = b0;
            op[(r + 64) * 128 + wl + 64] = b1;
        }
    }
}

// ---------------------------------------------------------------------------
extern "C" void kernel_launch(void* const* d_in, const int* in_sizes, int n_in,
                              void* d_out, int out_size) {
    const float* X   = (const float*)d_in[0];
    const float* w0r = (const float*)d_in[1];
    const float* w0i = (const float*)d_in[2];
    const float* w1r = (const float*)d_in[3];
    const float* w1i = (const float*)d_in[4];
    float* out = (float*)d_out;

    static bool attr_done = false;
    if (!attr_done) {
        cudaFuncSetAttribute(k_modes, cudaFuncAttributeMaxDynamicSharedMemorySize,
                             91136);
        attr_done = true;
    }

    k_transpose<<<2048, 256>>>(w0r, w0i, w1r, w1i);
    k_forward<<<1024, 128>>>(X);
    k_modes<<<512, 256, 91136>>>();
    k_inverse<<<1024, 256>>>(out);
}